// round 1
// baseline (speedup 1.0000x reference)
#include <cuda_runtime.h>

// Spline1DInterpolant: y_b = sum_i c[i] * u(|s_b + 2 - (i+1)|), s = (x-a)/h, h=(b-a)/n
// u has compact support (t<2) -> exactly 4 contributing coefficients per query.
//
// Inputs (metadata order): x[B,1] f32, a[1] f32, b[1] f32, n[1] f32, c[4096] f32
// Output: y[B] f32

__device__ __forceinline__ float basis(float t) {
    // t >= 0 assumed
    float inner = 4.0f + t * t * (-6.0f + 3.0f * t);   // t <= 1
    float om = 2.0f - t;
    float outer = om * om * om;                         // 1 < t <= 2
    float u = (t <= 1.0f) ? inner : outer;
    return (t < 2.0f) ? u : 0.0f;
}

__global__ void spline1d_kernel(const float* __restrict__ x,
                                const float* __restrict__ a,
                                const float* __restrict__ b,
                                const float* __restrict__ n,
                                const float* __restrict__ c,
                                float* __restrict__ out,
                                int B, int C) {
    int tid = blockIdx.x * blockDim.x + threadIdx.x;
    if (tid >= B) return;

    float av = a[0];
    float inv_h = n[0] / (b[0] - av);      // 1/h = n/(b-a)
    float s = (x[tid] - av) * inv_h;

    // contributing i (1-based): i in (s, s+4)  ->  i = floor(s)+1 .. floor(s)+4
    int ib = (int)floorf(s);

    float acc = 0.0f;
#pragma unroll
    for (int k = 1; k <= 4; ++k) {
        int i = ib + k;                    // 1-based coefficient index
        int idx = i - 1;                   // c index
        float t = fabsf(s + 2.0f - (float)i);
        if (idx >= 0 && idx < C) {
            acc += c[idx] * basis(t);
        }
    }
    out[tid] = acc;
}

extern "C" void kernel_launch(void* const* d_in, const int* in_sizes, int n_in,
                              void* d_out, int out_size) {
    const float* x = (const float*)d_in[0];
    const float* a = (const float*)d_in[1];
    const float* b = (const float*)d_in[2];
    const float* n = (const float*)d_in[3];
    const float* c = (const float*)d_in[4];
    float* out = (float*)d_out;

    int B = in_sizes[0];
    int C = in_sizes[4];

    int threads = 256;
    int blocks = (B + threads - 1) / threads;
    spline1d_kernel<<<blocks, threads>>>(x, a, b, n, c, out, B, C);
}